// round 1
// baseline (speedup 1.0000x reference)
#include <cuda_runtime.h>
#include <mma.h>
#include <cstdint>

using namespace nvcuda;

#define B_SZ   128
#define T_SZ   256
#define DIN    1024
#define UNITS  1024
#define NG     4096   // 4*UNITS
#define NCLASS 1024

// ---------------- scratch (device globals; no allocation allowed) ----------------
__device__ float g_XP[(size_t)B_SZ * T_SZ * NG];   // 512 MiB: xp for all timesteps
__device__ float g_hbuf0[B_SZ * UNITS];
__device__ float g_hbuf1[B_SZ * UNITS];
__device__ float g_cbuf[B_SZ * UNITS];

__device__ __forceinline__ float sigmf(float x) { return 1.f / (1.f + __expf(-x)); }

// =====================================================================
// Kernel 1: XP = X @ Wk   (M=32768, N=4096, K=1024) row-major, tf32 WMMA
// bias bk is folded in later (step kernel epilogue).
// =====================================================================
#define XBM 128
#define XBN 128
#define XBK 32

__global__ void xp_gemm_kernel(const float* __restrict__ A,   // [32768,1024]
                               const float* __restrict__ Bm,  // [1024,4096]
                               float* __restrict__ C)         // [32768,4096]
{
    __shared__ float As[XBM][XBK + 8];   // ld 40
    __shared__ float Bs[XBK][XBN + 8];   // ld 136

    const int bm = blockIdx.y;
    const int bn = blockIdx.x;
    const int tid = threadIdx.x;
    const int wid = tid >> 5;
    const int wm = wid & 3;     // 4 warps over M (32 rows each)
    const int wn = wid >> 2;    // 2 warps over N (64 cols each)

    wmma::fragment<wmma::accumulator, 16, 16, 8, float> acc[2][4];
#pragma unroll
    for (int i = 0; i < 2; i++)
#pragma unroll
        for (int j = 0; j < 4; j++) wmma::fill_fragment(acc[i][j], 0.0f);

    for (int k0 = 0; k0 < DIN; k0 += XBK) {
        // load A tile 128x32 (1024 float4)
#pragma unroll
        for (int i = tid; i < XBM * (XBK / 4); i += 256) {
            int r = i >> 3, cv = i & 7;
            float4 v = *(const float4*)&A[(size_t)(bm * XBM + r) * DIN + k0 + cv * 4];
            As[r][cv * 4 + 0] = v.x; As[r][cv * 4 + 1] = v.y;
            As[r][cv * 4 + 2] = v.z; As[r][cv * 4 + 3] = v.w;
        }
        // load B tile 32x128 (1024 float4)
#pragma unroll
        for (int i = tid; i < XBK * (XBN / 4); i += 256) {
            int r = i >> 5, cv = i & 31;
            float4 v = *(const float4*)&Bm[(size_t)(k0 + r) * NG + bn * XBN + cv * 4];
            Bs[r][cv * 4 + 0] = v.x; Bs[r][cv * 4 + 1] = v.y;
            Bs[r][cv * 4 + 2] = v.z; Bs[r][cv * 4 + 3] = v.w;
        }
        __syncthreads();

#pragma unroll
        for (int kk = 0; kk < XBK; kk += 8) {
            wmma::fragment<wmma::matrix_a, 16, 16, 8, wmma::precision::tf32, wmma::row_major> af[2];
            wmma::fragment<wmma::matrix_b, 16, 16, 8, wmma::precision::tf32, wmma::row_major> bf[4];
#pragma unroll
            for (int i = 0; i < 2; i++) {
                wmma::load_matrix_sync(af[i], &As[wm * 32 + i * 16][kk], XBK + 8);
#pragma unroll
                for (int e = 0; e < af[i].num_elements; e++)
                    af[i].x[e] = wmma::__float_to_tf32(af[i].x[e]);
            }
#pragma unroll
            for (int j = 0; j < 4; j++) {
                wmma::load_matrix_sync(bf[j], &Bs[kk][wn * 64 + j * 16], XBN + 8);
#pragma unroll
                for (int e = 0; e < bf[j].num_elements; e++)
                    bf[j].x[e] = wmma::__float_to_tf32(bf[j].x[e]);
            }
#pragma unroll
            for (int i = 0; i < 2; i++)
#pragma unroll
                for (int j = 0; j < 4; j++)
                    wmma::mma_sync(acc[i][j], af[i], bf[j], acc[i][j]);
        }
        __syncthreads();
    }

#pragma unroll
    for (int i = 0; i < 2; i++)
#pragma unroll
        for (int j = 0; j < 4; j++) {
            size_t row = (size_t)(bm * XBM + wm * 32 + i * 16);
            size_t col = (size_t)(bn * XBN + wn * 64 + j * 16);
            wmma::store_matrix_sync(&C[row * NG + col], acc[i][j], NG, wmma::mem_row_major);
        }
}

// =====================================================================
// Kernel 2: one recurrence step.
// CTA computes hp for rows [b0,b0+64) and cols {g*1024+u0+u : g<4, u<16},
// then fuses MI gating + c/h update in the epilogue.
// grid: (UNITS/16=64, B/64=2), 256 threads.
// =====================================================================
#define SBM 64
#define SBU 16
#define SBN 64   // 4 gates * SBU
#define SBK 32

__global__ void step_kernel(int t,
                            const float* __restrict__ hcur,
                            float* __restrict__ hnext,
                            float* __restrict__ cbuf,
                            const float* __restrict__ Wr,    // [1024,4096]
                            const float* __restrict__ br,
                            const float* __restrict__ bk,
                            const float* __restrict__ alpha,
                            const float* __restrict__ beta1,
                            const float* __restrict__ beta2,
                            const float* __restrict__ XP)
{
    __shared__ float As[SBM][SBK + 8];   // ld 40
    __shared__ float Bs[SBK][SBN + 8];   // ld 72
    __shared__ float Zs[SBM][SBN + 8];   // ld 72

    const int u0 = blockIdx.x * SBU;
    const int b0 = blockIdx.y * SBM;
    const int tid = threadIdx.x;
    const int wid = tid >> 5;
    const int wm = wid & 3;    // 4 warps over M (16 rows each)
    const int wn = wid >> 2;   // 2 warps over N (32 cols each)

    wmma::fragment<wmma::accumulator, 16, 16, 8, float> acc[2];
    wmma::fill_fragment(acc[0], 0.0f);
    wmma::fill_fragment(acc[1], 0.0f);

    for (int k0 = 0; k0 < UNITS; k0 += SBK) {
        // A tile: h rows 64 x 32 k  (512 float4)
#pragma unroll
        for (int i = tid; i < SBM * (SBK / 4); i += 256) {
            int r = i >> 3, cv = i & 7;
            float4 v = *(const float4*)&hcur[(size_t)(b0 + r) * UNITS + k0 + cv * 4];
            As[r][cv * 4 + 0] = v.x; As[r][cv * 4 + 1] = v.y;
            As[r][cv * 4 + 2] = v.z; As[r][cv * 4 + 3] = v.w;
        }
        // B tile: Wr 32 k x 64 grouped cols (512 float4)
#pragma unroll
        for (int i = tid; i < SBK * (SBN / 4); i += 256) {
            int r = i >> 4, c4 = i & 15;
            int gate = c4 >> 2;
            int j = gate * UNITS + u0 + (c4 & 3) * 4;
            float4 v = *(const float4*)&Wr[(size_t)(k0 + r) * NG + j];
            Bs[r][c4 * 4 + 0] = v.x; Bs[r][c4 * 4 + 1] = v.y;
            Bs[r][c4 * 4 + 2] = v.z; Bs[r][c4 * 4 + 3] = v.w;
        }
        __syncthreads();

#pragma unroll
        for (int kk = 0; kk < SBK; kk += 8) {
            wmma::fragment<wmma::matrix_a, 16, 16, 8, wmma::precision::tf32, wmma::row_major> af;
            wmma::fragment<wmma::matrix_b, 16, 16, 8, wmma::precision::tf32, wmma::row_major> bf[2];
            wmma::load_matrix_sync(af, &As[wm * 16][kk], SBK + 8);
#pragma unroll
            for (int e = 0; e < af.num_elements; e++) af.x[e] = wmma::__float_to_tf32(af.x[e]);
#pragma unroll
            for (int j = 0; j < 2; j++) {
                wmma::load_matrix_sync(bf[j], &Bs[kk][wn * 32 + j * 16], SBN + 8);
#pragma unroll
                for (int e = 0; e < bf[j].num_elements; e++)
                    bf[j].x[e] = wmma::__float_to_tf32(bf[j].x[e]);
                wmma::mma_sync(acc[j], af, bf[j], acc[j]);
            }
        }
        __syncthreads();
    }

    // dump hp tile to smem
    wmma::store_matrix_sync(&Zs[wm * 16][wn * 32 + 0],  acc[0], SBN + 8, wmma::mem_row_major);
    wmma::store_matrix_sync(&Zs[wm * 16][wn * 32 + 16], acc[1], SBN + 8, wmma::mem_row_major);
    __syncthreads();

    // fused MI gating + state update. 64 rows x 16 u = 1024 items.
    for (int e = tid; e < SBM * SBU; e += 256) {
        int r = e >> 4, u = e & 15;
        int b = b0 + r;
        int uu = u0 + u;
        const float* xp_row = &XP[((size_t)b * T_SZ + t) * NG];
        float z[4];
#pragma unroll
        for (int g = 0; g < 4; g++) {
            int j = g * UNITS + uu;
            float hp = Zs[r][g * SBU + u] + br[j];
            float xv = xp_row[j] + bk[j];
            z[g] = alpha[j] * xv * hp + beta1[j] * xv + beta2[j] * hp;
        }
        float cold = cbuf[(size_t)b * UNITS + uu];
        float cn = tanhf(z[2]) * sigmf(z[0]) + cold * sigmf(z[1]);
        float hn = tanhf(cn) * sigmf(z[3]);
        cbuf[(size_t)b * UNITS + uu] = cn;
        hnext[(size_t)b * UNITS + uu] = hn;
    }
}

// =====================================================================
// Kernel 3: out = h @ Wc + bc  (fp32 naive; 134 MFLOP, exact)
// grid: (NCLASS/256, B), 256 threads
// =====================================================================
__global__ void classify_kernel(const float* __restrict__ h,
                                const float* __restrict__ Wc,
                                const float* __restrict__ bc,
                                float* __restrict__ out)
{
    int col = blockIdx.x * 256 + threadIdx.x;
    int b = blockIdx.y;
    const float* hr = &h[(size_t)b * UNITS];
    float s = 0.f;
#pragma unroll 8
    for (int k = 0; k < UNITS; k++)
        s += hr[k] * Wc[(size_t)k * NCLASS + col];
    out[(size_t)b * NCLASS + col] = s + bc[col];
}

// =====================================================================
// launch
// =====================================================================
extern "C" void kernel_launch(void* const* d_in, const int* in_sizes, int n_in,
                              void* d_out, int out_size)
{
    const float* x     = (const float*)d_in[0];
    const float* h0    = (const float*)d_in[1];
    const float* c0    = (const float*)d_in[2];
    const float* Wk    = (const float*)d_in[3];
    const float* bk    = (const float*)d_in[4];
    const float* Wr    = (const float*)d_in[5];
    const float* br    = (const float*)d_in[6];
    const float* alpha = (const float*)d_in[7];
    const float* beta1 = (const float*)d_in[8];
    const float* beta2 = (const float*)d_in[9];
    const float* Wc    = (const float*)d_in[10];
    const float* bc    = (const float*)d_in[11];
    float* out = (float*)d_out;

    float *pXP, *pH0, *pH1, *pC;
    cudaGetSymbolAddress((void**)&pXP, g_XP);
    cudaGetSymbolAddress((void**)&pH0, g_hbuf0);
    cudaGetSymbolAddress((void**)&pH1, g_hbuf1);
    cudaGetSymbolAddress((void**)&pC,  g_cbuf);

    const size_t stateBytes = (size_t)B_SZ * UNITS * sizeof(float);
    cudaMemcpyAsync(pH0, h0, stateBytes, cudaMemcpyDeviceToDevice);
    cudaMemcpyAsync(pC,  c0, stateBytes, cudaMemcpyDeviceToDevice);

    // hoisted input projection for all timesteps
    xp_gemm_kernel<<<dim3(NG / XBN, (B_SZ * T_SZ) / XBM), 256>>>(x, Wk, pXP);

    // sequential recurrence
    float* hc = pH0;
    float* hn = pH1;
    for (int t = 0; t < T_SZ; t++) {
        step_kernel<<<dim3(UNITS / SBU, B_SZ / SBM), 256>>>(
            t, hc, hn, pC, Wr, br, bk, alpha, beta1, beta2, pXP);
        float* tmp = hc; hc = hn; hn = tmp;
    }

    // classifier + emit (out, h, c)
    classify_kernel<<<dim3(NCLASS / 256, B_SZ), 256>>>(hc, Wc, bc, out);
    cudaMemcpyAsync(out + (size_t)B_SZ * NCLASS, hc, stateBytes, cudaMemcpyDeviceToDevice);
    cudaMemcpyAsync(out + (size_t)B_SZ * NCLASS + (size_t)B_SZ * UNITS, pC, stateBytes,
                    cudaMemcpyDeviceToDevice);
}

// round 2
// speedup vs baseline: 1.0269x; 1.0269x over previous
#include <cuda_runtime.h>
#include <mma.h>
#include <cstdint>

using namespace nvcuda;

#define B_SZ   128
#define T_SZ   256
#define DIN    1024
#define UNITS  1024
#define NG     4096
#define NCLASS 1024

// ---------------- scratch ----------------
__device__ float g_XP[(size_t)B_SZ * T_SZ * NG];
__device__ float g_hbuf0[B_SZ * UNITS];
__device__ float g_hbuf1[B_SZ * UNITS];
__device__ float g_cbuf[B_SZ * UNITS];

__device__ __forceinline__ float sigmf(float x) { return 1.f / (1.f + __expf(-x)); }

__device__ __forceinline__ uint32_t smem_u32(const void* p) {
    return (uint32_t)__cvta_generic_to_shared(p);
}
#define CP16(dst, src) asm volatile("cp.async.cg.shared.global [%0], [%1], 16;\n" :: "r"(dst), "l"(src))
#define CPC()  asm volatile("cp.async.commit_group;\n")
#define CPW1() asm volatile("cp.async.wait_group 1;\n")
#define CPW0() asm volatile("cp.async.wait_group 0;\n")

extern __shared__ float smem[];

// =====================================================================
// XP = X @ Wk : M=32768, N=4096, K=1024. tf32 WMMA, 3-stage cp.async.
// 256 threads, warps 4(M)x2(N), warp tile 32x64, CTA tile 128x128x32.
// =====================================================================
#define XALD 36
#define XBLD 132
#define X_ABUF (128 * XALD)   // floats
#define X_BBUF (32 * XBLD)
#define XP_SMEM_BYTES (3 * (X_ABUF + X_BBUF) * 4)

__global__ __launch_bounds__(256) void xp_gemm_kernel(const float* __restrict__ A,
                                                      const float* __restrict__ Bm,
                                                      float* __restrict__ C)
{
    float* As = smem;
    float* Bs = smem + 3 * X_ABUF;

    const int bm = blockIdx.y;
    const int bn = blockIdx.x;
    const int tid = threadIdx.x;
    const int wid = tid >> 5;
    const int wm = wid & 3;
    const int wn = wid >> 2;

    const float* aBase = A + (size_t)(bm * 128) * DIN;
    const float* bBase = Bm + bn * 128;

    wmma::fragment<wmma::accumulator, 16, 16, 8, float> acc[2][4];
#pragma unroll
    for (int i = 0; i < 2; i++)
#pragma unroll
        for (int j = 0; j < 4; j++) wmma::fill_fragment(acc[i][j], 0.0f);

    auto load_chunk = [&](int k, int s) {
        float* ad = As + s * X_ABUF;
        const float* asrc = aBase + k * 32;
#pragma unroll
        for (int i = 0; i < 4; i++) {
            int idx = tid + i * 256;
            int r = idx >> 3, c = idx & 7;
            CP16(smem_u32(ad + r * XALD + c * 4), asrc + (size_t)r * DIN + c * 4);
        }
        float* bd = Bs + s * X_BBUF;
        const float* bsrc = bBase + (size_t)(k * 32) * NG;
#pragma unroll
        for (int i = 0; i < 4; i++) {
            int idx = tid + i * 256;
            int r = idx >> 5, c = idx & 31;
            CP16(smem_u32(bd + r * XBLD + c * 4), bsrc + (size_t)r * NG + c * 4);
        }
        CPC();
    };

    load_chunk(0, 0);
    load_chunk(1, 1);

    for (int k = 0; k < 32; k++) {
        if (k < 31) { CPW1(); } else { CPW0(); }
        __syncthreads();
        if (k + 2 < 32) load_chunk(k + 2, (k + 2) % 3);

        const float* ab = As + (k % 3) * X_ABUF;
        const float* bb = Bs + (k % 3) * X_BBUF;
#pragma unroll
        for (int kk = 0; kk < 32; kk += 8) {
            wmma::fragment<wmma::matrix_a, 16, 16, 8, wmma::precision::tf32, wmma::row_major> af[2];
            wmma::fragment<wmma::matrix_b, 16, 16, 8, wmma::precision::tf32, wmma::row_major> bf[4];
#pragma unroll
            for (int i = 0; i < 2; i++) {
                wmma::load_matrix_sync(af[i], ab + (wm * 32 + i * 16) * XALD + kk, XALD);
#pragma unroll
                for (int e = 0; e < af[i].num_elements; e++)
                    af[i].x[e] = wmma::__float_to_tf32(af[i].x[e]);
            }
#pragma unroll
            for (int j = 0; j < 4; j++) {
                wmma::load_matrix_sync(bf[j], bb + kk * XBLD + wn * 64 + j * 16, XBLD);
#pragma unroll
                for (int e = 0; e < bf[j].num_elements; e++)
                    bf[j].x[e] = wmma::__float_to_tf32(bf[j].x[e]);
            }
#pragma unroll
            for (int i = 0; i < 2; i++)
#pragma unroll
                for (int j = 0; j < 4; j++)
                    wmma::mma_sync(acc[i][j], af[i], bf[j], acc[i][j]);
        }
        __syncthreads();
    }

#pragma unroll
    for (int i = 0; i < 2; i++)
#pragma unroll
        for (int j = 0; j < 4; j++) {
            size_t row = (size_t)(bm * 128 + wm * 32 + i * 16);
            size_t col = (size_t)(bn * 128 + wn * 64 + j * 16);
            wmma::store_matrix_sync(&C[row * NG + col], acc[i][j], NG, wmma::mem_row_major);
        }
}

// =====================================================================
// Step kernel: hp = h @ Wr for 64 batch rows x (16 units x 4 gates),
// fused MI gating + c/h update. 128 threads, warps 2x2, warp tile 32x32,
// CTA tile 64x64x32, 3-stage cp.async pipeline.
// grid: (64, 2)
// =====================================================================
#define S_ALD 36
#define S_BLD 68
#define S_ABUF (64 * S_ALD)
#define S_BBUF (32 * S_BLD)
#define STEP_SMEM_BYTES (3 * (S_ABUF + S_BBUF) * 4)

__global__ __launch_bounds__(128) void step_kernel(int t,
                            const float* __restrict__ hcur,
                            float* __restrict__ hnext,
                            float* __restrict__ cbuf,
                            const float* __restrict__ Wr,
                            const float* __restrict__ br,
                            const float* __restrict__ bk,
                            const float* __restrict__ alpha,
                            const float* __restrict__ beta1,
                            const float* __restrict__ beta2,
                            const float* __restrict__ XP)
{
    float* As = smem;
    float* Bs = smem + 3 * S_ABUF;

    const int u0 = blockIdx.x * 16;
    const int b0 = blockIdx.y * 64;
    const int tid = threadIdx.x;
    const int wid = tid >> 5;
    const int wm = wid & 1;
    const int wn = wid >> 1;

    const float* aBase = hcur + (size_t)b0 * UNITS;

    wmma::fragment<wmma::accumulator, 16, 16, 8, float> acc[2][2];
#pragma unroll
    for (int i = 0; i < 2; i++)
#pragma unroll
        for (int j = 0; j < 2; j++) wmma::fill_fragment(acc[i][j], 0.0f);

    auto load_chunk = [&](int k, int s) {
        float* ad = As + s * S_ABUF;
        const float* asrc = aBase + k * 32;
#pragma unroll
        for (int i = 0; i < 4; i++) {
            int idx = tid + i * 128;
            int r = idx >> 3, c = idx & 7;
            CP16(smem_u32(ad + r * S_ALD + c * 4), asrc + (size_t)r * UNITS + c * 4);
        }
        float* bd = Bs + s * S_BBUF;
        const float* bsrc = Wr + (size_t)(k * 32) * NG;
#pragma unroll
        for (int i = 0; i < 4; i++) {
            int idx = tid + i * 128;
            int r = idx >> 4, c4 = idx & 15;
            int col = (c4 >> 2) * UNITS + u0 + (c4 & 3) * 4;
            CP16(smem_u32(bd + r * S_BLD + c4 * 4), bsrc + (size_t)r * NG + col);
        }
        CPC();
    };

    load_chunk(0, 0);
    load_chunk(1, 1);

    for (int k = 0; k < 32; k++) {
        if (k < 31) { CPW1(); } else { CPW0(); }
        __syncthreads();
        if (k + 2 < 32) load_chunk(k + 2, (k + 2) % 3);

        const float* ab = As + (k % 3) * S_ABUF;
        const float* bb = Bs + (k % 3) * S_BBUF;
#pragma unroll
        for (int kk = 0; kk < 32; kk += 8) {
            wmma::fragment<wmma::matrix_a, 16, 16, 8, wmma::precision::tf32, wmma::row_major> af[2];
            wmma::fragment<wmma::matrix_b, 16, 16, 8, wmma::precision::tf32, wmma::row_major> bf[2];
#pragma unroll
            for (int i = 0; i < 2; i++) {
                wmma::load_matrix_sync(af[i], ab + (wm * 32 + i * 16) * S_ALD + kk, S_ALD);
#pragma unroll
                for (int e = 0; e < af[i].num_elements; e++)
                    af[i].x[e] = wmma::__float_to_tf32(af[i].x[e]);
            }
#pragma unroll
            for (int j = 0; j < 2; j++) {
                wmma::load_matrix_sync(bf[j], bb + kk * S_BLD + wn * 32 + j * 16, S_BLD);
#pragma unroll
                for (int e = 0; e < bf[j].num_elements; e++)
                    bf[j].x[e] = wmma::__float_to_tf32(bf[j].x[e]);
            }
#pragma unroll
            for (int i = 0; i < 2; i++)
#pragma unroll
                for (int j = 0; j < 2; j++)
                    wmma::mma_sync(acc[i][j], af[i], bf[j], acc[i][j]);
        }
        __syncthreads();
    }

    // dump hp tile (reuse As region as Zs, ld 68)
    float* Zs = As;
#pragma unroll
    for (int i = 0; i < 2; i++)
#pragma unroll
        for (int j = 0; j < 2; j++)
            wmma::store_matrix_sync(Zs + (wm * 32 + i * 16) * 68 + wn * 32 + j * 16,
                                    acc[i][j], 68, wmma::mem_row_major);
    __syncthreads();

    // fused MI gating + state update: 64 rows x 16 units
    for (int e = tid; e < 64 * 16; e += 128) {
        int r = e >> 4, u = e & 15;
        int b = b0 + r;
        int uu = u0 + u;
        const float* xp_row = &XP[((size_t)b * T_SZ + t) * NG];
        float z[4];
#pragma unroll
        for (int g = 0; g < 4; g++) {
            int j = g * UNITS + uu;
            float hp = Zs[r * 68 + g * 16 + u] + br[j];
            float xv = xp_row[j] + bk[j];
            z[g] = alpha[j] * xv * hp + beta1[j] * xv + beta2[j] * hp;
        }
        float cold = cbuf[(size_t)b * UNITS + uu];
        float cn = tanhf(z[2]) * sigmf(z[0]) + cold * sigmf(z[1]);
        float hn = tanhf(cn) * sigmf(z[3]);
        cbuf[(size_t)b * UNITS + uu] = cn;
        hnext[(size_t)b * UNITS + uu] = hn;
    }
}

// =====================================================================
// classifier: out = h @ Wc + bc (fp32, exact)
// =====================================================================
__global__ void classify_kernel(const float* __restrict__ h,
                                const float* __restrict__ Wc,
                                const float* __restrict__ bc,
                                float* __restrict__ out)
{
    int col = blockIdx.x * 256 + threadIdx.x;
    int b = blockIdx.y;
    const float* hr = &h[(size_t)b * UNITS];
    float s = 0.f;
#pragma unroll 8
    for (int k = 0; k < UNITS; k++)
        s += hr[k] * Wc[(size_t)k * NCLASS + col];
    out[(size_t)b * NCLASS + col] = s + bc[col];
}

// =====================================================================
// launch
// =====================================================================
extern "C" void kernel_launch(void* const* d_in, const int* in_sizes, int n_in,
                              void* d_out, int out_size)
{
    const float* x     = (const float*)d_in[0];
    const float* h0    = (const float*)d_in[1];
    const float* c0    = (const float*)d_in[2];
    const float* Wk    = (const float*)d_in[3];
    const float* bk    = (const float*)d_in[4];
    const float* Wr    = (const float*)d_in[5];
    const float* br    = (const float*)d_in[6];
    const float* alpha = (const float*)d_in[7];
    const float* beta1 = (const float*)d_in[8];
    const float* beta2 = (const float*)d_in[9];
    const float* Wc    = (const float*)d_in[10];
    const float* bc    = (const float*)d_in[11];
    float* out = (float*)d_out;

    float *pXP, *pH0, *pH1, *pC;
    cudaGetSymbolAddress((void**)&pXP, g_XP);
    cudaGetSymbolAddress((void**)&pH0, g_hbuf0);
    cudaGetSymbolAddress((void**)&pH1, g_hbuf1);
    cudaGetSymbolAddress((void**)&pC,  g_cbuf);

    static bool attr_done = false;
    if (!attr_done) {
        cudaFuncSetAttribute(xp_gemm_kernel, cudaFuncAttributeMaxDynamicSharedMemorySize, XP_SMEM_BYTES);
        cudaFuncSetAttribute(step_kernel, cudaFuncAttributeMaxDynamicSharedMemorySize, STEP_SMEM_BYTES);
        attr_done = true;
    }

    const size_t stateBytes = (size_t)B_SZ * UNITS * sizeof(float);
    cudaMemcpyAsync(pH0, h0, stateBytes, cudaMemcpyDeviceToDevice);
    cudaMemcpyAsync(pC,  c0, stateBytes, cudaMemcpyDeviceToDevice);

    xp_gemm_kernel<<<dim3(NG / 128, (B_SZ * T_SZ) / 128), 256, XP_SMEM_BYTES>>>(x, Wk, pXP);

    float* hc = pH0;
    float* hn = pH1;
    for (int t = 0; t < T_SZ; t++) {
        step_kernel<<<dim3(UNITS / 16, B_SZ / 64), 128, STEP_SMEM_BYTES>>>(
            t, hc, hn, pC, Wr, br, bk, alpha, beta1, beta2, pXP);
        float* tmp = hc; hc = hn; hn = tmp;
    }

    classify_kernel<<<dim3(NCLASS / 256, B_SZ), 256>>>(hc, Wc, bc, out);
    cudaMemcpyAsync(out + (size_t)B_SZ * NCLASS, hc, stateBytes, cudaMemcpyDeviceToDevice);
    cudaMemcpyAsync(out + (size_t)B_SZ * NCLASS + (size_t)B_SZ * UNITS, pC, stateBytes,
                    cudaMemcpyDeviceToDevice);
}

// round 3
// speedup vs baseline: 1.3370x; 1.3020x over previous
#include <cuda_runtime.h>
#include <mma.h>
#include <cstdint>

using namespace nvcuda;

#define B_SZ   128
#define T_SZ   256
#define DIN    1024
#define UNITS  1024
#define NG     4096
#define NCLASS 1024

// ---------------- scratch ----------------
__device__ float g_XP[(size_t)B_SZ * T_SZ * NG];   // xp for all timesteps
__device__ float g_hT0[UNITS * B_SZ];              // transposed h ping
__device__ float g_hT1[UNITS * B_SZ];              // transposed h pong
__device__ float g_hrow[B_SZ * UNITS];             // final h, row-major, unrounded
__device__ float g_cbuf[B_SZ * UNITS];             // final c
__device__ unsigned g_bar_count;
__device__ unsigned g_bar_epoch;

__device__ __forceinline__ float sigmf(float x) { return 1.f / (1.f + __expf(-x)); }
__device__ __forceinline__ float tf32r(float x) { return wmma::__float_to_tf32(x); }

__device__ __forceinline__ uint32_t smem_u32(const void* p) {
    return (uint32_t)__cvta_generic_to_shared(p);
}
#define CP16(dst, src) asm volatile("cp.async.cg.shared.global [%0], [%1], 16;\n" :: "r"(dst), "l"(src))
#define CPC()  asm volatile("cp.async.commit_group;\n")
#define CPW1() asm volatile("cp.async.wait_group 1;\n")
#define CPW0() asm volatile("cp.async.wait_group 0;\n")

extern __shared__ float smem[];

// =====================================================================
// XP = X @ Wk : M=32768, N=4096, K=1024 (tf32 WMMA, 3-stage cp.async)
// =====================================================================
#define XALD 36
#define XBLD 132
#define X_ABUF (128 * XALD)
#define X_BBUF (32 * XBLD)
#define XP_SMEM_BYTES (3 * (X_ABUF + X_BBUF) * 4)

__global__ __launch_bounds__(256) void xp_gemm_kernel(const float* __restrict__ A,
                                                      const float* __restrict__ Bm,
                                                      float* __restrict__ C)
{
    float* As = smem;
    float* Bs = smem + 3 * X_ABUF;

    const int bm = blockIdx.y;
    const int bn = blockIdx.x;
    const int tid = threadIdx.x;
    const int wid = tid >> 5;
    const int wm = wid & 3;
    const int wn = wid >> 2;

    const float* aBase = A + (size_t)(bm * 128) * DIN;
    const float* bBase = Bm + bn * 128;

    wmma::fragment<wmma::accumulator, 16, 16, 8, float> acc[2][4];
#pragma unroll
    for (int i = 0; i < 2; i++)
#pragma unroll
        for (int j = 0; j < 4; j++) wmma::fill_fragment(acc[i][j], 0.0f);

    auto load_chunk = [&](int k, int s) {
        float* ad = As + s * X_ABUF;
        const float* asrc = aBase + k * 32;
#pragma unroll
        for (int i = 0; i < 4; i++) {
            int idx = tid + i * 256;
            int r = idx >> 3, c = idx & 7;
            CP16(smem_u32(ad + r * XALD + c * 4), asrc + (size_t)r * DIN + c * 4);
        }
        float* bd = Bs + s * X_BBUF;
        const float* bsrc = bBase + (size_t)(k * 32) * NG;
#pragma unroll
        for (int i = 0; i < 4; i++) {
            int idx = tid + i * 256;
            int r = idx >> 5, c = idx & 31;
            CP16(smem_u32(bd + r * XBLD + c * 4), bsrc + (size_t)r * NG + c * 4);
        }
        CPC();
    };

    load_chunk(0, 0);
    load_chunk(1, 1);

    for (int k = 0; k < 32; k++) {
        if (k < 31) { CPW1(); } else { CPW0(); }
        __syncthreads();
        if (k + 2 < 32) load_chunk(k + 2, (k + 2) % 3);

        const float* ab = As + (k % 3) * X_ABUF;
        const float* bb = Bs + (k % 3) * X_BBUF;
#pragma unroll
        for (int kk = 0; kk < 32; kk += 8) {
            wmma::fragment<wmma::matrix_a, 16, 16, 8, wmma::precision::tf32, wmma::row_major> af[2];
            wmma::fragment<wmma::matrix_b, 16, 16, 8, wmma::precision::tf32, wmma::row_major> bf[4];
#pragma unroll
            for (int i = 0; i < 2; i++) {
                wmma::load_matrix_sync(af[i], ab + (wm * 32 + i * 16) * XALD + kk, XALD);
#pragma unroll
                for (int e = 0; e < af[i].num_elements; e++)
                    af[i].x[e] = wmma::__float_to_tf32(af[i].x[e]);
            }
#pragma unroll
            for (int j = 0; j < 4; j++) {
                wmma::load_matrix_sync(bf[j], bb + kk * XBLD + wn * 64 + j * 16, XBLD);
#pragma unroll
                for (int e = 0; e < bf[j].num_elements; e++)
                    bf[j].x[e] = wmma::__float_to_tf32(bf[j].x[e]);
            }
#pragma unroll
            for (int i = 0; i < 2; i++)
#pragma unroll
                for (int j = 0; j < 4; j++)
                    wmma::mma_sync(acc[i][j], af[i], bf[j], acc[i][j]);
        }
        __syncthreads();
    }

#pragma unroll
    for (int i = 0; i < 2; i++)
#pragma unroll
        for (int j = 0; j < 4; j++) {
            size_t row = (size_t)(bm * 128 + wm * 32 + i * 16);
            size_t col = (size_t)(bn * 128 + wn * 64 + j * 16);
            wmma::store_matrix_sync(&C[row * NG + col], acc[i][j], NG, wmma::mem_row_major);
        }
}

// =====================================================================
// h0 transpose: hT[u][b] = tf32(h0[b][u])
// =====================================================================
__global__ void transpose_h0_kernel(const float* __restrict__ h0, float* __restrict__ hT)
{
    int u = blockIdx.x;
    int b = threadIdx.x;
    hT[u * B_SZ + b] = tf32r(h0[(size_t)b * UNITS + u]);
}

// =====================================================================
// Persistent recurrence kernel.
// 128 CTAs x 256 threads. CTA owns units [u0, u0+8) => 32 gate-columns.
// Wr slice resident in smem for all 256 steps; c in registers.
// =====================================================================
#define UPC 8           // units per CTA
#define NGC 32          // gate-cols per CTA
#define WSLD 36
#define HLD  132
#define KC   32         // k-chunk
#define NCH  (UNITS / KC)

#define OFF_WS 0
#define WS_SZ  (UNITS * WSLD)                 // 36864
#define OFF_HS (OFF_WS + WS_SZ)
#define HS_STG (KC * HLD)                     // 4224
#define HS_SZ  (3 * HS_STG)                   // 12672
#define OFF_XS (OFF_HS + HS_SZ)
#define XS_SZ  (B_SZ * 36)                    // 4608
#define OFF_P  (OFF_XS + XS_SZ)
#define P_SZ   (5 * NGC)                      // 160
#define PERS_SMEM_BYTES ((OFF_P + P_SZ) * 4)  // 217216 B

__global__ __launch_bounds__(256, 1) void persistent_lstm_kernel(
    const float* __restrict__ Wr,
    const float* __restrict__ br,
    const float* __restrict__ bk,
    const float* __restrict__ alpha,
    const float* __restrict__ beta1,
    const float* __restrict__ beta2,
    const float* __restrict__ c0)
{
    float* Ws = smem + OFF_WS;
    float* Hs = smem + OFF_HS;
    float* Xs = smem + OFF_XS;
    float* Pbk = smem + OFF_P;
    float* Pbr = Pbk + NGC;
    float* Pal = Pbr + NGC;
    float* Pb1 = Pal + NGC;
    float* Pb2 = Pb1 + NGC;

    const int tid = threadIdx.x;
    const int wid = tid >> 5;
    const int wm = wid & 3;     // 4 warps over M(batch): 32 rows each
    const int wn = wid >> 2;    // 2 warps over N: 16 cols each
    const int u0 = blockIdx.x * UPC;

    // ---- prologue: Wr slice -> smem (tf32-rounded) ----
    for (int it = 0; it < 32; it++) {
        int i = tid + it * 256;            // 8192 float4
        int k = i >> 3, q = i & 7;
        int g = q >> 1, part = q & 1;
        const float4 v = *(const float4*)&Wr[(size_t)k * NG + g * UNITS + u0 + part * 4];
        float* d = Ws + k * WSLD + g * UPC + part * 4;
        d[0] = tf32r(v.x); d[1] = tf32r(v.y); d[2] = tf32r(v.z); d[3] = tf32r(v.w);
    }
    if (tid < NGC) {
        int g = tid >> 3, j = tid & 7;
        int jj = g * UNITS + u0 + j;
        Pbk[tid] = bk[jj]; Pbr[tid] = br[jj];
        Pal[tid] = alpha[jj]; Pb1[tid] = beta1[jj]; Pb2[tid] = beta2[jj];
    }
    // c in registers: thread owns (u = tid>>5, b = (tid&31)*4 .. +3)
    const int cu = tid >> 5;
    const int cb0 = (tid & 31) * 4;
    float creg[4];
#pragma unroll
    for (int i = 0; i < 4; i++)
        creg[i] = c0[(size_t)(cb0 + i) * UNITS + u0 + cu];
    __syncthreads();

    // ---- time loop ----
    for (int t = 0; t < T_SZ; t++) {
        const float* hT = (t & 1) ? g_hT1 : g_hT0;
        float* hTn = (t & 1) ? g_hT0 : g_hT1;

        wmma::fragment<wmma::accumulator, 16, 16, 8, float> acc[2];
        wmma::fill_fragment(acc[0], 0.0f);
        wmma::fill_fragment(acc[1], 0.0f);

        auto load_chunk = [&](int kc, int s) {
            float* hd = Hs + s * HS_STG;
            const float* hsrc = hT + kc * KC * B_SZ;
#pragma unroll
            for (int j = 0; j < 4; j++) {
                int i = tid + j * 256;      // 1024 float4
                int kr = i >> 5, bc = (i & 31) * 4;
                CP16(smem_u32(hd + kr * HLD + bc), hsrc + kr * B_SZ + bc);
            }
            if (kc == 0) {
                // xp tile for this step rides with chunk 0's group
#pragma unroll
                for (int j = 0; j < 4; j++) {
                    int i = tid + j * 256;  // 1024 float4
                    int b = i >> 3, q = i & 7;
                    int g = q >> 1, part = q & 1;
                    CP16(smem_u32(Xs + b * 36 + g * UPC + part * 4),
                         g_XP + ((size_t)b * T_SZ + t) * NG + g * UNITS + u0 + part * 4);
                }
            }
            CPC();
        };

        load_chunk(0, 0);
        load_chunk(1, 1);

        for (int kc = 0; kc < NCH; kc++) {
            if (kc < NCH - 1) { CPW1(); } else { CPW0(); }
            __syncthreads();
            if (kc + 2 < NCH) load_chunk(kc + 2, (kc + 2) % 3);

            const float* hb = Hs + (kc % 3) * HS_STG;
            const float* wb = Ws + kc * KC * WSLD;
#pragma unroll
            for (int kk = 0; kk < KC; kk += 8) {
                wmma::fragment<wmma::matrix_a, 16, 16, 8, wmma::precision::tf32, wmma::col_major> af[2];
                wmma::fragment<wmma::matrix_b, 16, 16, 8, wmma::precision::tf32, wmma::row_major> bf;
                wmma::load_matrix_sync(af[0], hb + kk * HLD + wm * 32, HLD);
                wmma::load_matrix_sync(af[1], hb + kk * HLD + wm * 32 + 16, HLD);
                wmma::load_matrix_sync(bf, wb + kk * WSLD + wn * 16, WSLD);
                wmma::mma_sync(acc[0], af[0], bf, acc[0]);
                wmma::mma_sync(acc[1], af[1], bf, acc[1]);
            }
        }
        __syncthreads();   // all chunks consumed; Hs free for reuse

        // dump hp tile [128 b][32 cols] into Zs (= Hs base, ld 36)
        float* Zs = Hs;
        wmma::store_matrix_sync(Zs + (wm * 32) * 36 + wn * 16, acc[0], 36, wmma::mem_row_major);
        wmma::store_matrix_sync(Zs + (wm * 32 + 16) * 36 + wn * 16, acc[1], 36, wmma::mem_row_major);
        __syncthreads();

        // pointwise: thread owns u=cu, b=cb0..cb0+3
        float hout[4];
#pragma unroll
        for (int i = 0; i < 4; i++) {
            int b = cb0 + i;
            float z[4];
#pragma unroll
            for (int g = 0; g < 4; g++) {
                int cc = g * UPC + cu;
                float hp = Zs[b * 36 + cc] + Pbr[cc];
                float xv = Xs[b * 36 + cc] + Pbk[cc];
                z[g] = Pal[cc] * xv * hp + Pb1[cc] * xv + Pb2[cc] * hp;
            }
            float cn = tanhf(z[2]) * sigmf(z[0]) + creg[i] * sigmf(z[1]);
            float hn = tanhf(cn) * sigmf(z[3]);
            creg[i] = cn;
            hout[i] = hn;
        }
        // coalesced write of rounded h (one 512B row per warp)
        float4 hv = make_float4(tf32r(hout[0]), tf32r(hout[1]), tf32r(hout[2]), tf32r(hout[3]));
        *(float4*)&hTn[(u0 + cu) * B_SZ + cb0] = hv;

        if (t == T_SZ - 1) {
#pragma unroll
            for (int i = 0; i < 4; i++) {
                g_hrow[(size_t)(cb0 + i) * UNITS + u0 + cu] = hout[i];
                g_cbuf[(size_t)(cb0 + i) * UNITS + u0 + cu] = creg[i];
            }
        }

        // grid barrier
        __threadfence();
        __syncthreads();
        if (tid == 0) {
            unsigned arr = atomicAdd(&g_bar_count, 1u);
            if (arr == gridDim.x - 1) {
                atomicExch(&g_bar_count, 0u);
                __threadfence();
                atomicAdd(&g_bar_epoch, 1u);
            } else {
                volatile unsigned* ep = &g_bar_epoch;
                while (*ep < (unsigned)(t + 1)) __nanosleep(64);
            }
        }
        __syncthreads();
    }
}

// =====================================================================
// classifier: out = h @ Wc + bc (fp32, exact)
// =====================================================================
__global__ void classify_kernel(const float* __restrict__ h,
                                const float* __restrict__ Wc,
                                const float* __restrict__ bc,
                                float* __restrict__ out)
{
    int col = blockIdx.x * 256 + threadIdx.x;
    int b = blockIdx.y;
    const float* hr = &h[(size_t)b * UNITS];
    float s = 0.f;
#pragma unroll 8
    for (int k = 0; k < UNITS; k++)
        s += hr[k] * Wc[(size_t)k * NCLASS + col];
    out[(size_t)b * NCLASS + col] = s + bc[col];
}

// =====================================================================
// launch
// =====================================================================
extern "C" void kernel_launch(void* const* d_in, const int* in_sizes, int n_in,
                              void* d_out, int out_size)
{
    const float* x     = (const float*)d_in[0];
    const float* h0    = (const float*)d_in[1];
    const float* c0    = (const float*)d_in[2];
    const float* Wk    = (const float*)d_in[3];
    const float* bk    = (const float*)d_in[4];
    const float* Wr    = (const float*)d_in[5];
    const float* br    = (const float*)d_in[6];
    const float* alpha = (const float*)d_in[7];
    const float* beta1 = (const float*)d_in[8];
    const float* beta2 = (const float*)d_in[9];
    const float* Wc    = (const float*)d_in[10];
    const float* bc    = (const float*)d_in[11];
    float* out = (float*)d_out;

    float *pXP, *pHT0, *pHrow, *pC;
    cudaGetSymbolAddress((void**)&pXP, g_XP);
    cudaGetSymbolAddress((void**)&pHT0, g_hT0);
    cudaGetSymbolAddress((void**)&pHrow, g_hrow);
    cudaGetSymbolAddress((void**)&pC, g_cbuf);
    unsigned *pCnt, *pEp;
    cudaGetSymbolAddress((void**)&pCnt, g_bar_count);
    cudaGetSymbolAddress((void**)&pEp, g_bar_epoch);

    cudaFuncSetAttribute(xp_gemm_kernel, cudaFuncAttributeMaxDynamicSharedMemorySize, XP_SMEM_BYTES);
    cudaFuncSetAttribute(persistent_lstm_kernel, cudaFuncAttributeMaxDynamicSharedMemorySize, PERS_SMEM_BYTES);

    cudaMemsetAsync(pCnt, 0, sizeof(unsigned));
    cudaMemsetAsync(pEp, 0, sizeof(unsigned));

    transpose_h0_kernel<<<UNITS, B_SZ>>>(h0, pHT0);
    xp_gemm_kernel<<<dim3(NG / 128, (B_SZ * T_SZ) / 128), 256, XP_SMEM_BYTES>>>(x, Wk, pXP);

    persistent_lstm_kernel<<<UNITS / UPC, 256, PERS_SMEM_BYTES>>>(
        Wr, br, bk, alpha, beta1, beta2, c0);

    classify_kernel<<<dim3(NCLASS / 256, B_SZ), 256>>>(pHrow, Wc, bc, out);

    const size_t stateBytes = (size_t)B_SZ * UNITS * sizeof(float);
    cudaMemcpyAsync(out + (size_t)B_SZ * NCLASS, pHrow, stateBytes, cudaMemcpyDeviceToDevice);
    cudaMemcpyAsync(out + (size_t)B_SZ * NCLASS + (size_t)B_SZ * UNITS, pC, stateBytes,
                    cudaMemcpyDeviceToDevice);
}

// round 5
// speedup vs baseline: 3.9888x; 2.9834x over previous
#include <cuda_runtime.h>
#include <cuda_fp16.h>
#include <mma.h>
#include <cstdint>
#include <cstring>

using namespace nvcuda;

#define B_SZ   128
#define T_SZ   256
#define DIN    1024
#define UNITS  1024
#define NG     4096
#define NCLASS 1024

// ---------------- scratch ----------------
__device__ float  g_XP[(size_t)B_SZ * T_SZ * NG];     // xp fp32, all timesteps
__device__ __half g_xh[(size_t)B_SZ * T_SZ * DIN];    // x in fp16
__device__ __half g_wkh[(size_t)DIN * NG];            // Wk in fp16
__device__ __half g_hT0[UNITS * B_SZ];                // transposed h fp16 ping
__device__ __half g_hT1[UNITS * B_SZ];                // transposed h fp16 pong
__device__ float  g_hrow[B_SZ * UNITS];               // final h fp32 row-major
__device__ float  g_cbuf[B_SZ * UNITS];               // final c fp32
__device__ unsigned g_bar_count;
__device__ unsigned g_bar_epoch;

__device__ __forceinline__ float sigmf(float x) { return 1.f / (1.f + __expf(-x)); }

__device__ __forceinline__ uint32_t smem_u32(const void* p) {
    return (uint32_t)__cvta_generic_to_shared(p);
}
#define CP16(dst, src) asm volatile("cp.async.cg.shared.global [%0], [%1], 16;\n" :: "r"(dst), "l"(src))
#define CPC()  asm volatile("cp.async.commit_group;\n")
#define CPW1() asm volatile("cp.async.wait_group 1;\n")
#define CPW0() asm volatile("cp.async.wait_group 0;\n")

extern __shared__ float smem[];

// =====================================================================
// float -> half conversion (grid-stride, 4 elems/thread)
// =====================================================================
__global__ void f2h_kernel(const float* __restrict__ src, __half* __restrict__ dst, int n4)
{
    int i = blockIdx.x * blockDim.x + threadIdx.x;
    if (i < n4) {
        float4 v = *(const float4*)(src + (size_t)i * 4);
        __half2 a = __floats2half2_rn(v.x, v.y);
        __half2 b = __floats2half2_rn(v.z, v.w);
        uint2 pk;
        memcpy(&pk.x, &a, 4); memcpy(&pk.y, &b, 4);
        *(uint2*)(dst + (size_t)i * 4) = pk;
    }
}

// h0 -> transposed fp16: hT[u][b]
__global__ void h0_to_hT_kernel(const float* __restrict__ h0, __half* __restrict__ hT)
{
    int u = blockIdx.x;
    int b = threadIdx.x;
    hT[u * B_SZ + b] = __float2half(h0[(size_t)b * UNITS + u]);
}

// =====================================================================
// XP = X @ Wk : M=32768, N=4096, K=1024. fp16 WMMA m16n16k16, 3-stage.
// CTA tile 128x128xK64. 256 threads, warps 4(M)x2(N), warp 32x64.
// =====================================================================
#define XALD 72    // halfs: 64 + 8
#define XBLD 136   // halfs: 128 + 8
#define X_ABUF (128 * XALD)              // halfs per stage
#define X_BBUF (64 * XBLD)
#define XP_SMEM_BYTES (3 * (X_ABUF + X_BBUF) * 2)

__global__ __launch_bounds__(256) void xp_gemm_kernel(const __half* __restrict__ A,
                                                      const __half* __restrict__ Bm,
                                                      float* __restrict__ C)
{
    __half* As = (__half*)smem;
    __half* Bs = As + 3 * X_ABUF;

    const int bm = blockIdx.y, bn = blockIdx.x;
    const int tid = threadIdx.x, wid = tid >> 5;
    const int wm = wid & 3, wn = wid >> 2;
    const __half* aBase = A + (size_t)(bm * 128) * DIN;
    const __half* bBase = Bm + bn * 128;

    wmma::fragment<wmma::accumulator, 16, 16, 16, float> acc[2][4];
#pragma unroll
    for (int i = 0; i < 2; i++)
#pragma unroll
        for (int j = 0; j < 4; j++) wmma::fill_fragment(acc[i][j], 0.0f);

    auto load_chunk = [&](int k, int s) {
        __half* ad = As + s * X_ABUF;
        const __half* asrc = aBase + k * 64;
#pragma unroll
        for (int i = 0; i < 4; i++) {
            int idx = tid + i * 256;          // 1024 x 16B
            int r = idx >> 3, c8 = idx & 7;
            CP16(smem_u32(ad + r * XALD + c8 * 8), asrc + (size_t)r * DIN + c8 * 8);
        }
        __half* bd = Bs + s * X_BBUF;
        const __half* bsrc = bBase + (size_t)(k * 64) * NG;
#pragma unroll
        for (int i = 0; i < 4; i++) {
            int idx = tid + i * 256;          // 1024 x 16B
            int r = idx >> 4, c8 = idx & 15;
            CP16(smem_u32(bd + r * XBLD + c8 * 8), bsrc + (size_t)r * NG + c8 * 8);
        }
        CPC();
    };

    load_chunk(0, 0);
    load_chunk(1, 1);

    for (int k = 0; k < 16; k++) {
        if (k < 15) { CPW1(); } else { CPW0(); }
        __syncthreads();
        if (k + 2 < 16) load_chunk(k + 2, (k + 2) % 3);

        const __half* ab = As + (k % 3) * X_ABUF;
        const __half* bb = Bs + (k % 3) * X_BBUF;
#pragma unroll
        for (int kk = 0; kk < 64; kk += 16) {
            wmma::fragment<wmma::matrix_a, 16, 16, 16, __half, wmma::row_major> af[2];
            wmma::fragment<wmma::matrix_b, 16, 16, 16, __half, wmma::row_major> bf[4];
#pragma unroll
            for (int i = 0; i < 2; i++)
                wmma::load_matrix_sync(af[i], ab + (wm * 32 + i * 16) * XALD + kk, XALD);
#pragma unroll
            for (int j = 0; j < 4; j++)
                wmma::load_matrix_sync(bf[j], bb + kk * XBLD + wn * 64 + j * 16, XBLD);
#pragma unroll
            for (int i = 0; i < 2; i++)
#pragma unroll
                for (int j = 0; j < 4; j++)
                    wmma::mma_sync(acc[i][j], af[i], bf[j], acc[i][j]);
        }
        __syncthreads();
    }

#pragma unroll
    for (int i = 0; i < 2; i++)
#pragma unroll
        for (int j = 0; j < 4; j++) {
            size_t row = (size_t)(bm * 128 + wm * 32 + i * 16);
            size_t col = (size_t)(bn * 128 + wn * 64 + j * 16);
            wmma::store_matrix_sync(&C[row * NG + col], acc[i][j], NG, wmma::mem_row_major);
        }
}

// =====================================================================
// Persistent recurrence, fp16 WMMA.
// 128 CTAs x 256 threads. CTA: units [u0,u0+8) => 32 gate-cols, M=128, K=1024.
// Wr slice resident in smem fp16 (80 KB). h transposed fp16, ping-pong.
// warps: 4 over M (32 rows), 2 over N (16 cols); warp tile 32x16.
// =====================================================================
#define WSLD 40                          // halfs: 32 + 8
#define HLD  136                         // halfs: 128 + 8
#define KC   64
#define NCH  (UNITS / KC)                // 16

#define WS_HALFS (UNITS * WSLD)          // 40960 halfs = 80 KB
#define HS_STG   (KC * HLD)              // 8704 halfs = 17408 B
#define HS_HALFS (3 * HS_STG)
#define XS_FLTS  (B_SZ * 36)             // 4608 floats = 18 KB
#define P_FLTS   (5 * 32)

#define OFF_WS_H 0
#define OFF_HS_H (OFF_WS_H + WS_HALFS)
#define OFF_XS_F ((OFF_HS_H + HS_HALFS + 1) / 2)        // float index
#define OFF_P_F  (OFF_XS_F + XS_FLTS)
#define PERS_SMEM_BYTES ((OFF_P_F + P_FLTS) * 4)

__global__ __launch_bounds__(256, 1) void persistent_lstm_kernel(
    const float* __restrict__ Wr,
    const float* __restrict__ br,
    const float* __restrict__ bk,
    const float* __restrict__ alpha,
    const float* __restrict__ beta1,
    const float* __restrict__ beta2,
    const float* __restrict__ c0)
{
    __half* Ws = (__half*)smem;
    __half* Hs = Ws + OFF_HS_H;
    float* Xs  = smem + OFF_XS_F;
    float* Pbk = smem + OFF_P_F;
    float* Pbr = Pbk + 32;
    float* Pal = Pbr + 32;
    float* Pb1 = Pal + 32;
    float* Pb2 = Pb1 + 32;

    const int tid = threadIdx.x;
    const int wid = tid >> 5;
    const int wm = wid & 3;      // 4 warps over M: 32 rows each
    const int wn = wid >> 2;     // 2 warps over N: 16 cols each
    const int u0 = blockIdx.x * 8;

    // ---- prologue: Wr slice -> smem fp16, layout [k][n] ld 40 ----
    for (int it = 0; it < 128; it++) {
        int idx = tid + it * 256;         // 32768
        int n = idx & 31, k = idx >> 5;
        Ws[k * WSLD + n] = __float2half(Wr[(size_t)k * NG + (n >> 3) * UNITS + u0 + (n & 7)]);
    }
    if (tid < 32) {
        int jj = (tid >> 3) * UNITS + u0 + (tid & 7);
        Pbk[tid] = bk[jj]; Pbr[tid] = br[jj];
        Pal[tid] = alpha[jj]; Pb1[tid] = beta1[jj]; Pb2[tid] = beta2[jj];
    }
    // c registers: thread owns unit cu = tid>>5 (0..7), batch rows cb0..cb0+3
    const int cu = tid >> 5;
    const int cb0 = (tid & 31) * 4;
    float creg[4];
#pragma unroll
    for (int i = 0; i < 4; i++)
        creg[i] = c0[(size_t)(cb0 + i) * UNITS + u0 + cu];
    __syncthreads();

    // ---- time loop ----
    for (int t = 0; t < T_SZ; t++) {
        const __half* hT = (t & 1) ? g_hT1 : g_hT0;
        __half* hTn = (t & 1) ? g_hT0 : g_hT1;

        wmma::fragment<wmma::accumulator, 16, 16, 16, float> acc[2];
        wmma::fill_fragment(acc[0], 0.0f);
        wmma::fill_fragment(acc[1], 0.0f);

        auto load_chunk = [&](int kc, int s) {
            __half* hd = Hs + s * HS_STG;
            const __half* hsrc = hT + kc * KC * B_SZ;
#pragma unroll
            for (int j = 0; j < 4; j++) {
                int i = tid + j * 256;        // 1024 x 16B
                int kr = i >> 4, b8 = (i & 15) * 8;
                CP16(smem_u32(hd + kr * HLD + b8), hsrc + kr * B_SZ + b8);
            }
            if (kc == 0) {
                // xp tile [128 b][32 gc] rides with chunk 0
#pragma unroll
                for (int j = 0; j < 4; j++) {
                    int i = tid + j * 256;    // 1024 x 16B
                    int b = i >> 3, q = i & 7;
                    int g = q >> 1, part = q & 1;
                    CP16(smem_u32(Xs + b * 36 + g * 8 + part * 4),
                         g_XP + ((size_t)b * T_SZ + t) * NG + g * UNITS + u0 + part * 4);
                }
            }
            CPC();
        };

        load_chunk(0, 0);
        load_chunk(1, 1);

        for (int kc = 0; kc < NCH; kc++) {
            if (kc < NCH - 1) { CPW1(); } else { CPW0(); }
            __syncthreads();
            if (kc + 2 < NCH) load_chunk(kc + 2, (kc + 2) % 3);

            const __half* hb = Hs + (kc % 3) * HS_STG;
            const __half* wb = Ws + kc * KC * WSLD;
#pragma unroll
            for (int kk = 0; kk < KC; kk += 16) {
                wmma::fragment<wmma::matrix_a, 16, 16, 16, __half, wmma::col_major> af[2];
                wmma::fragment<wmma::matrix_b, 16, 16, 16, __half, wmma::row_major> bf;
                wmma::load_matrix_sync(af[0], hb + kk * HLD + wm * 32, HLD);
                wmma::load_matrix_sync(af[1], hb + kk * HLD + wm * 32 + 16, HLD);
                wmma::load_matrix_sync(bf, wb + kk * WSLD + wn * 16, WSLD);
                wmma::mma_sync(acc[0], af[0], bf, acc[0]);
                wmma::mma_sync(acc[1], af[1], bf, acc[1]);
            }
        }
        __syncthreads();   // Hs free

        // dump hp tile [128][32] -> Zs (reuse Hs), ld 36 floats
        float* Zs = (float*)Hs;
        wmma::store_matrix_sync(Zs + (wm * 32) * 36 + wn * 16, acc[0], 36, wmma::mem_row_major);
        wmma::store_matrix_sync(Zs + (wm * 32 + 16) * 36 + wn * 16, acc[1], 36, wmma::mem_row_major);
        __syncthreads();

        // pointwise: thread owns u=cu, b=cb0..cb0+3
        float hout[4];
#pragma unroll
        for (int i = 0; i < 4; i++) {
            int b = cb0 + i;
            float z[4];
#pragma unroll
            for (int g = 0; g < 4; g++) {
                int cc = g * 8 + cu;
                float hp = Zs[b * 36 + cc] + Pbr[cc];
                float xv = Xs[b * 36 + cc] + Pbk[cc];
                z[g] = Pal[cc] * xv * hp + Pb1[cc] * xv + Pb2[cc] * hp;
            }
            float cn = tanhf(z[2]) * sigmf(z[0]) + creg[i] * sigmf(z[1]);
            float hn = tanhf(cn) * sigmf(z[3]);
            creg[i] = cn;
            hout[i] = hn;
        }
        // coalesced fp16 write: 4 halfs (8B) per thread, consecutive lanes
        __half2 p0 = __floats2half2_rn(hout[0], hout[1]);
        __half2 p1 = __floats2half2_rn(hout[2], hout[3]);
        uint2 pk;
        memcpy(&pk.x, &p0, 4); memcpy(&pk.y, &p1, 4);
        *(uint2*)(hTn + (u0 + cu) * B_SZ + cb0) = pk;

        if (t == T_SZ - 1) {
#pragma unroll
            for (int i = 0; i < 4; i++) {
                g_hrow[(size_t)(cb0 + i) * UNITS + u0 + cu] = hout[i];
                g_cbuf[(size_t)(cb0 + i) * UNITS + u0 + cu] = creg[i];
            }
        }

        // grid barrier
        __threadfence();
        __syncthreads();
        if (tid == 0) {
            unsigned arr = atomicAdd(&g_bar_count, 1u);
            if (arr == gridDim.x - 1) {
                atomicExch(&g_bar_count, 0u);
                __threadfence();
                atomicAdd(&g_bar_epoch, 1u);
            } else {
                volatile unsigned* ep = &g_bar_epoch;
                while (*ep < (unsigned)(t + 1)) __nanosleep(64);
            }
        }
        __syncthreads();
    }
}

// =====================================================================
// classifier: out = h @ Wc + bc (fp32, exact)
// =====================================================================
__global__ void classify_kernel(const float* __restrict__ h,
                                const float* __restrict__ Wc,
                                const float* __restrict__ bc,
                                float* __restrict__ out)
{
    int col = blockIdx.x * 256 + threadIdx.x;
    int b = blockIdx.y;
    const float* hr = &h[(size_t)b * UNITS];
    float s = 0.f;
#pragma unroll 8
    for (int k = 0; k < UNITS; k++)
        s += hr[k] * Wc[(size_t)k * NCLASS + col];
    out[(size_t)b * NCLASS + col] = s + bc[col];
}

// =====================================================================
// launch
// =====================================================================
extern "C" void kernel_launch(void* const* d_in, const int* in_sizes, int n_in,
                              void* d_out, int out_size)
{
    const float* x     = (const float*)d_in[0];
    const float* h0    = (const float*)d_in[1];
    const float* c0    = (const float*)d_in[2];
    const float* Wk    = (const float*)d_in[3];
    const float* bk    = (const float*)d_in[4];
    const float* Wr    = (const float*)d_in[5];
    const float* br    = (const float*)d_in[6];
    const float* alpha = (const float*)d_in[7];
    const float* beta1 = (const float*)d_in[8];
    const float* beta2 = (const float*)d_in[9];
    const float* Wc    = (const float*)d_in[10];
    const float* bc    = (const float*)d_in[11];
    float* out = (float*)d_out;

    float *pXP, *pHrow, *pC;
    __half *pXH, *pWKH, *pHT0;
    cudaGetSymbolAddress((void**)&pXP, g_XP);
    cudaGetSymbolAddress((void**)&pXH, g_xh);
    cudaGetSymbolAddress((void**)&pWKH, g_wkh);
    cudaGetSymbolAddress((void**)&pHT0, g_hT0);
    cudaGetSymbolAddress((void**)&pHrow, g_hrow);
    cudaGetSymbolAddress((void**)&pC, g_cbuf);
    unsigned *pCnt, *pEp;
    cudaGetSymbolAddress((void**)&pCnt, g_bar_count);
    cudaGetSymbolAddress((void**)&pEp, g_bar_epoch);

    cudaFuncSetAttribute(xp_gemm_kernel, cudaFuncAttributeMaxDynamicSharedMemorySize, XP_SMEM_BYTES);
    cudaFuncSetAttribute(persistent_lstm_kernel, cudaFuncAttributeMaxDynamicSharedMemorySize, PERS_SMEM_BYTES);

    cudaMemsetAsync(pCnt, 0, sizeof(unsigned));
    cudaMemsetAsync(pEp, 0, sizeof(unsigned));

    // fp16 conversions
    f2h_kernel<<<(B_SZ * T_SZ * DIN / 4 + 255) / 256, 256>>>(x, pXH, B_SZ * T_SZ * DIN / 4);
    f2h_kernel<<<(DIN * NG / 4 + 255) / 256, 256>>>(Wk, pWKH, DIN * NG / 4);
    h0_to_hT_kernel<<<UNITS, B_SZ>>>(h0, pHT0);

    xp_gemm_kernel<<<dim3(NG / 128, (B_SZ * T_SZ) / 128), 256, XP_SMEM_BYTES>>>(pXH, pWKH, pXP);

    persistent_lstm_kernel<<<UNITS / 8, 256, PERS_SMEM_BYTES>>>(
        Wr, br, bk, alpha, beta1, beta2, c0);

    classify_kernel<<<dim3(NCLASS / 256, B_SZ), 256>>>(pHrow, Wc, bc, out);

    const size_t stateBytes = (size_t)B_SZ * UNITS * sizeof(float);
    cudaMemcpyAsync(out + (size_t)B_SZ * NCLASS, pHrow, stateBytes, cudaMemcpyDeviceToDevice);
    cudaMemcpyAsync(out + (size_t)B_SZ * NCLASS + (size_t)B_SZ * UNITS, pC, stateBytes,
                    cudaMemcpyDeviceToDevice);
}